// round 12
// baseline (speedup 1.0000x reference)
#include <cuda_runtime.h>
#include <cuda_fp16.h>
#include <math.h>
#include <stdint.h>

// VectorQuantizerEMA: D=64, K=512, N=B*T=262144.
// fp16 HMMA screen with running per-row top-2 -> 95% of rows need NO exact
// rescore (singleton candidate); ambiguous rows use staged warp rescore.
#define DIM 64
#define NCODES 512
#define TILE_M 128
#define TPB 256
#define MAXGRID 256
#define NCHUNK 32
#define CMIN_STRIDE 33
#define QCAP 4096
#define XSTRIDE 272
#define STG_STRIDE 4352

__device__ float g_part[MAXGRID];
__device__ unsigned int g_ticket;

// ---------- smem layout (bytes) ----------
#define OFF_AH     0                   // A fp16 [128 x 128B] SW128      (16384)
#define OFF_BH     16384               // B fp16 [512 x 128B] SW128      (65536)
#define OFF_X      81920               // x fp32 [128 x 272B]            (34816)
#define OFF_EEW    116736              // float4[512]: (ee, w, s, 0)     (8192)
#define OFF_CMIN   124928              // u64[128][33] packed (dist,k)   (33792)
#define OFF_ROWKEY 158720              // u64[128] row top-1 (dist,k)    (1024)
#define OFF_ROWM2  159744              // f32[128] row second-min        (512)
#define OFF_SXX    160256              // f32[128]                       (512)
#define OFF_BEST   160768              // u64[128]                       (1024)
#define OFF_QUEUE  161792              // u32[QCAP] chunk entries        (16384)
#define OFF_CNT    178176              // qn @+0, smax @+8               (16)
#define OFF_STAGE  178192              // 8 warps x 4352B                (34816)
#define OFF_RED    213008              // float[256]                     (1024)
#define SMEM_TOTAL 214032

#define SWZ(o) ((uint32_t)(o) ^ ((((uint32_t)(o)) >> 3) & 0x70))

typedef unsigned long long u64;

__device__ __forceinline__ uint32_t smem_u32(const void* p) {
    uint32_t a;
    asm("{ .reg .u64 t; cvta.to.shared.u64 t, %1; cvt.u32.u64 %0, t; }"
        : "=r"(a) : "l"(p));
    return a;
}
__device__ __forceinline__ void ldm4(uint32_t* r, uint32_t addr) {
    asm volatile("ldmatrix.sync.aligned.m8n8.x4.shared.b16 {%0,%1,%2,%3}, [%4];"
                 : "=r"(r[0]), "=r"(r[1]), "=r"(r[2]), "=r"(r[3]) : "r"(addr));
}
__device__ __forceinline__ void mma16816(float* c, const uint32_t* a,
                                         const uint32_t* b) {
    asm volatile(
        "mma.sync.aligned.m16n8k16.row.col.f32.f16.f16.f32 "
        "{%0,%1,%2,%3}, {%4,%5,%6,%7}, {%8,%9}, {%0,%1,%2,%3};"
        : "+f"(c[0]), "+f"(c[1]), "+f"(c[2]), "+f"(c[3])
        : "r"(a[0]), "r"(a[1]), "r"(a[2]), "r"(a[3]), "r"(b[0]), "r"(b[1]));
}
__device__ __forceinline__ uint32_t packh2(float a, float b) {
    __half2 h = __floats2half2_rn(a, b);
    return *(uint32_t*)&h;
}
__device__ __forceinline__ u64 pack64(float d, int k) {
    return ((u64)__float_as_uint(d) << 32) | (unsigned)k;
}
__device__ __forceinline__ float keyval(u64 k) {
    return __uint_as_float((uint32_t)(k >> 32));
}
__device__ __forceinline__ u64 umin64(u64 a, u64 b) { return a < b ? a : b; }

__global__ void __launch_bounds__(TPB, 1)
vq_hmma(const float* __restrict__ inputs,
        const float* __restrict__ emb,
        const float* __restrict__ ema,
        float* __restrict__ out_q,
        float* __restrict__ out_idx,
        float* __restrict__ out_loss,
        int ntiles, float inv_count) {
    extern __shared__ char smem[];
    const uint32_t sbase = smem_u32(smem);
    const int tid  = threadIdx.x;
    const int wid  = tid >> 5;
    const int lane = tid & 31;

    float4* eew   = (float4*)(smem + OFF_EEW);
    u64*    cmin64 = (u64*)(smem + OFF_CMIN);
    u64*    rowkey = (u64*)(smem + OFF_ROWKEY);
    float*  rowm2  = (float*)(smem + OFF_ROWM2);
    float*  sxx    = (float*)(smem + OFF_SXX);
    u64*    best64 = (u64*)(smem + OFF_BEST);
    uint32_t* queue = (uint32_t*)(smem + OFF_QUEUE);
    int* qn = (int*)(smem + OFF_CNT);

    if (tid == 0) *(int*)(smem + OFF_CNT + 8) = 0;
    __syncthreads();

    // ---- codebook init: fp16 plane + (ee, w, s); ee = serial fma chain ----
    for (int k = tid; k < NCODES; k += TPB) {
        const float* e = emb + k * DIM;
        float ee = 0.f;
#pragma unroll
        for (int d = 0; d < DIM; d++) ee += e[d] * e[d];
        const float4* ep = (const float4*)e;
#pragma unroll
        for (int q = 0; q < 16; q++) {
            float4 e4 = ep[q];
            uint2 hv = make_uint2(packh2(e4.x, e4.y), packh2(e4.z, e4.w));
            *(uint2*)(smem + OFF_BH + SWZ(k * 128 + q * 8)) = hv;
        }
        float w = sqrtf(ema[k]);
        float s = sqrtf(ee) * w;
        eew[k] = make_float4(ee, w, s, 0.f);
        atomicMax((int*)(smem + OFF_CNT + 8), __float_as_int(s));  // s >= 0
    }
    __syncthreads();
    const float smax = *(float*)(smem + OFF_CNT + 8);

    // fragment geometry
    const int R0 = wid * 16;
    const int rowA = R0 + ((lane >> 3) & 1) * 8 + (lane & 7);
    const uint32_t kaddA = ((lane >> 4) & 1) * 16;
    const int rowB = ((lane >> 4) & 1) * 8 + (lane & 7);
    const uint32_t kaddB = ((lane >> 3) & 1) * 16;
    const int rrow0 = R0 + (lane >> 2);
    const int rrow1 = rrow0 + 8;
    const int jcol  = (lane & 3) * 2;

    float lsum = 0.f;

    for (int tile = blockIdx.x; tile < ntiles; tile += gridDim.x) {
        const size_t base = (size_t)tile * TILE_M;
        __syncthreads();  // prev tile fully consumed

        // ---- A-build: x -> smem fp32 (padded) + fp16 plane ----
        if (tid < TILE_M) {
            const float4* xp = (const float4*)(inputs + (base + tid) * DIM);
            float4* xs = (float4*)(smem + OFF_X + tid * XSTRIDE);
            float xxr = 0.f;
#pragma unroll
            for (int q = 0; q < 16; q++) {
                float4 v = xp[q];
                xs[q] = v;
                xxr += v.x * v.x + v.y * v.y + v.z * v.z + v.w * v.w;
                uint2 hv = make_uint2(packh2(v.x, v.y), packh2(v.z, v.w));
                *(uint2*)(smem + OFF_AH + SWZ(tid * 128 + q * 8)) = hv;
            }
            sxx[tid] = xxr;
        }
        if (tid == 0) *qn = 0;
        __syncthreads();  // A ready

        // ---- screen GEMM (8 warps x 16 rows), 2 chunks per iter ----
        uint32_t ah[4][4];
#pragma unroll
        for (int s = 0; s < 4; s++)
            ldm4(ah[s], sbase + OFF_AH + SWZ(rowA * 128 + s * 32 + kaddA));

        const float xx0 = sxx[rrow0];
        const float xx1 = sxx[rrow1];
        u64 rkey0 = 0xFFFFFFFFFFFFFFFFull, rkey1 = 0xFFFFFFFFFFFFFFFFull;
        float rm2_0 = __int_as_float(0x7f800000);
        float rm2_1 = __int_as_float(0x7f800000);

#pragma unroll 1
        for (int c = 0; c < NCHUNK; c += 2) {
            const int n0 = c * 16;
            const int n1 = n0 + 16;
            float acc0[4] = {0.f, 0.f, 0.f, 0.f};
            float acc1[4] = {0.f, 0.f, 0.f, 0.f};
            float acc2[4] = {0.f, 0.f, 0.f, 0.f};
            float acc3[4] = {0.f, 0.f, 0.f, 0.f};
#pragma unroll
            for (int s = 0; s < 4; s++) {
                uint32_t bh0[4], bh1[4];
                ldm4(bh0, sbase + OFF_BH + SWZ((n0 + rowB) * 128 + s * 32 + kaddB));
                ldm4(bh1, sbase + OFF_BH + SWZ((n1 + rowB) * 128 + s * 32 + kaddB));
                mma16816(acc0, ah[s], bh0 + 0);
                mma16816(acc1, ah[s], bh0 + 2);
                mma16816(acc2, ah[s], bh1 + 0);
                mma16816(acc3, ah[s], bh1 + 2);
            }
#pragma unroll
            for (int half = 0; half < 2; half++) {
                const int nb = half ? n1 : n0;
                const int cc = c + half;
                float* a0 = half ? acc2 : acc0;
                float* a1 = half ? acc3 : acc1;
                const int c0 = nb + jcol;
                const int c2 = nb + jcol + 8;
                float4 e00 = eew[c0];
                float4 e01 = eew[c0 + 1];
                float4 e10 = eew[c2];
                float4 e11 = eew[c2 + 1];
                float w2a = -2.f * e00.y, w2b = -2.f * e01.y;
                float w2c = -2.f * e10.y, w2d = -2.f * e11.y;
                float d00 = fmaf(a0[0], w2a, (xx0 + e00.x) * e00.y);
                float d01 = fmaf(a0[1], w2b, (xx0 + e01.x) * e01.y);
                float d02 = fmaf(a1[0], w2c, (xx0 + e10.x) * e10.y);
                float d03 = fmaf(a1[1], w2d, (xx0 + e11.x) * e11.y);
                float d10 = fmaf(a0[2], w2a, (xx1 + e00.x) * e00.y);
                float d11 = fmaf(a0[3], w2b, (xx1 + e01.x) * e01.y);
                float d12 = fmaf(a1[2], w2c, (xx1 + e10.x) * e10.y);
                float d13 = fmaf(a1[3], w2d, (xx1 + e11.x) * e11.y);

                // ---- row 0: lane-local min(+arg) and second-min ----
                u64 lmin0 = umin64(umin64(pack64(d00, c0), pack64(d01, c0 + 1)),
                                   umin64(pack64(d02, c2), pack64(d03, c2 + 1)));
                float lo1 = fminf(d00, d01), hi1 = fmaxf(d00, d01);
                float lo2 = fminf(d02, d03), hi2 = fmaxf(d02, d03);
                float lm2 = fminf(fmaxf(lo1, lo2), fminf(hi1, hi2));
                // merge into running top-2 (values exact)
                rm2_0 = fminf(fminf(rm2_0, lm2),
                              fmaxf(keyval(rkey0), keyval(lmin0)));
                rkey0 = umin64(rkey0, lmin0);
                // cross-lane chunk min (4-lane group)
                u64 cm0 = lmin0;
                cm0 = umin64(cm0, __shfl_xor_sync(0xffffffffu, cm0, 1));
                cm0 = umin64(cm0, __shfl_xor_sync(0xffffffffu, cm0, 2));

                // ---- row 1 ----
                u64 lmin1 = umin64(umin64(pack64(d10, c0), pack64(d11, c0 + 1)),
                                   umin64(pack64(d12, c2), pack64(d13, c2 + 1)));
                float po1 = fminf(d10, d11), ph1 = fmaxf(d10, d11);
                float po2 = fminf(d12, d13), ph2 = fmaxf(d12, d13);
                float pm2 = fminf(fmaxf(po1, po2), fminf(ph1, ph2));
                rm2_1 = fminf(fminf(rm2_1, pm2),
                              fmaxf(keyval(rkey1), keyval(lmin1)));
                rkey1 = umin64(rkey1, lmin1);
                u64 cm1 = lmin1;
                cm1 = umin64(cm1, __shfl_xor_sync(0xffffffffu, cm1, 1));
                cm1 = umin64(cm1, __shfl_xor_sync(0xffffffffu, cm1, 2));

                if ((lane & 3) == 0) {
                    cmin64[rrow0 * CMIN_STRIDE + cc] = cm0;
                    cmin64[rrow1 * CMIN_STRIDE + cc] = cm1;
                }
            }
        }
        // final cross-lane top-2 merge (4-lane row group)
#pragma unroll
        for (int off = 1; off <= 2; off <<= 1) {
            u64 ok0 = __shfl_xor_sync(0xffffffffu, rkey0, off);
            float om0 = __shfl_xor_sync(0xffffffffu, rm2_0, off);
            rm2_0 = fminf(fminf(rm2_0, om0), fmaxf(keyval(rkey0), keyval(ok0)));
            rkey0 = umin64(rkey0, ok0);
            u64 ok1 = __shfl_xor_sync(0xffffffffu, rkey1, off);
            float om1 = __shfl_xor_sync(0xffffffffu, rm2_1, off);
            rm2_1 = fminf(fminf(rm2_1, om1), fmaxf(keyval(rkey1), keyval(ok1)));
            rkey1 = umin64(rkey1, ok1);
        }
        if ((lane & 3) == 0) {
            rowkey[rrow0] = rkey0;  rowm2[rrow0] = rm2_0;
            rowkey[rrow1] = rkey1;  rowm2[rrow1] = rm2_1;
        }
        __syncthreads();  // cmin/rowtop ready

        // ---- phase 2a: per-row classification ----
        if (tid < TILE_M) {
            u64 bkey = rowkey[tid];
            float m2 = rowm2[tid];
            float errmax = fmaf(2.5e-3f, sqrtf(sxx[tid]) * smax, 1e-2f);
            float thr = keyval(bkey) + 2.f * errmax;
            if (m2 > thr) {
                // singleton candidate: argmin is already exact, no rescore
                best64[tid] = bkey;
            } else {
                best64[tid] = 0xFFFFFFFFFFFFFFFFull;
#pragma unroll 1
                for (int c = 0; c < NCHUNK; c++) {
                    if (keyval(cmin64[tid * CMIN_STRIDE + c]) <= thr) {
                        int slot = atomicAdd(qn, 1);
                        if (slot < QCAP)
                            queue[slot] = ((uint32_t)tid << 5) | (uint32_t)c;
                    }
                }
            }
        }
        __syncthreads();  // queue + best init ready

        // ---- staged warp rescore of ambiguous chunks (exact fp32) ----
        {
            int nent = *qn;
            if (nent > QCAP) nent = QCAP;
            float4* stg = (float4*)(smem + OFF_STAGE + wid * STG_STRIDE);
#pragma unroll 1
            for (int e = wid; e < nent; e += 8) {
                uint32_t ent = queue[e];
                int row = (int)(ent >> 5);
                int c = (int)(ent & 31);
                const float4* src = (const float4*)(emb + (c << 10));
#pragma unroll
                for (int j = 0; j < 8; j++) {
                    float4 v = __ldg(src + j * 32 + lane);
                    int jj = j * 32 + lane;
                    stg[(jj >> 4) * 17 + (jj & 15)] = v;
                }
                __syncwarp();
                u64 key = 0xFFFFFFFFFFFFFFFFull;
                if (lane < 16) {
                    const float4* xs = (const float4*)(smem + OFF_X + row * XSTRIDE);
                    const float4* ep = stg + lane * 17;
                    float s0 = 0.f, s1 = 0.f, s2 = 0.f, s3 = 0.f;
#pragma unroll
                    for (int q = 0; q < 16; q++) {
                        float4 e4 = ep[q];
                        float4 x4 = xs[q];
                        s0 = fmaf(x4.x, e4.x, s0);
                        s1 = fmaf(x4.y, e4.y, s1);
                        s2 = fmaf(x4.z, e4.z, s2);
                        s3 = fmaf(x4.w, e4.w, s3);
                    }
                    float d = (s0 + s1) + (s2 + s3);
                    int k = (c << 4) + lane;
                    float4 ew = eew[k];
                    float t = (sxx[row] + ew.x - 2.0f * d) * ew.y;
                    key = pack64(t, k);
                }
#pragma unroll
                for (int off = 16; off > 0; off >>= 1) {
                    u64 o = __shfl_xor_sync(0xffffffffu, key, off);
                    if (o < key) key = o;
                }
                if (lane == 0) atomicMin(&best64[row], key);
                __syncwarp();
            }
        }
        __syncthreads();  // best ready

        // ---- outputs: coalesced cooperative write + loss ----
        for (int idx = tid; idx < TILE_M * 16; idx += TPB) {
            int row = idx >> 4, q = idx & 15;
            int bk = (int)(best64[row] & 0x1ff);
            float4 e4 = __ldg((const float4*)(emb + bk * DIM) + q);
            float4 x4 = *(const float4*)(smem + OFF_X + row * XSTRIDE + q * 16);
            float dx = x4.x - e4.x, dy = x4.y - e4.y;
            float dz = x4.z - e4.z, dw = x4.w - e4.w;
            lsum += dx * dx + dy * dy + dz * dz + dw * dw;
            *((float4*)(out_q + (base + row) * DIM) + q) = e4;
            if (q == 0) out_idx[base + row] = (float)bk;
        }
    }

    // ---- loss block reduction ----
    __syncthreads();
    float* red = (float*)(smem + OFF_RED);
    red[tid] = lsum;
    __syncthreads();
#pragma unroll
    for (int s = TPB / 2; s > 0; s >>= 1) {
        if (tid < s) red[tid] += red[tid + s];
        __syncthreads();
    }

    // ---- last-CTA finalize (deterministic ordered sum) ----
    __shared__ unsigned int s_ticket;
    if (tid == 0) {
        atomicExch(&g_part[blockIdx.x], red[0]);
        __threadfence();
        s_ticket = atomicAdd(&g_ticket, 1u);
    }
    __syncthreads();
    if ((s_ticket % gridDim.x) == gridDim.x - 1) {
        __threadfence();
        if (tid < (int)gridDim.x) red[tid] = atomicAdd(&g_part[tid], 0.0f);
        __syncthreads();
        if (tid == 0) {
            float s = 0.f;
            for (int i = 0; i < (int)gridDim.x; i++) s += red[i];
            out_loss[0] = 0.25f * s * inv_count;
        }
    }
}

extern "C" void kernel_launch(void* const* d_in, const int* in_sizes, int n_in,
                              void* d_out, int out_size) {
    const float* inputs = (const float*)d_in[0];
    const float* emb    = (const float*)d_in[1];
    const float* ema    = (const float*)d_in[2];

    int N = in_sizes[0] / DIM;
    int ntiles = N / TILE_M;
    float* out = (float*)d_out;
    float* out_q    = out;
    float* out_loss = out + (size_t)N * DIM;
    float* out_idx  = out + (size_t)N * DIM + 1;

    static int grid = 0;
    if (grid == 0) {
        int sms = 0;
        cudaDeviceGetAttribute(&sms, cudaDevAttrMultiProcessorCount, 0);
        grid = (sms > 0 && sms <= MAXGRID) ? sms : 148;
        cudaFuncSetAttribute(vq_hmma, cudaFuncAttributeMaxDynamicSharedMemorySize,
                             SMEM_TOTAL);
    }

    vq_hmma<<<grid, TPB, SMEM_TOTAL>>>(inputs, emb, ema, out_q, out_idx,
                                       out_loss, ntiles,
                                       1.0f / ((float)N * (float)DIM));
}